// round 14
// baseline (speedup 1.0000x reference)
#include <cuda_runtime.h>
#include <cuda_fp16.h>
#include <math.h>
#include <stdint.h>

// Problem constants
#define B_  8
#define T_  512
#define D_  512
#define H_  8
#define FF_ 2048
#define L_  6
#define CS_ 16
#define LC_ 4
#define DK_ 64
#define NCHUNK_ (T_ / CS_)          // 32
#define WMAX_ ((LC_ + 1) * CS_)     // 80
#define QKVN_ (3 * D_)              // 1536
#define PALLN_ (L_ * D_)            // 3072
#define AP_ 66                      // padded attention row pitch (halves)

// ---------------- scratch (device globals; no allocation) ----------------
__device__ float  g_x   [B_*T_*D_];
__device__ __half g_hh  [B_*T_*D_];     // LN output fp16
__device__ __half g_qkvh[B_*T_*QKVN_];
__device__ __half g_oh  [B_*T_*D_];
__device__ __half g_ffh [B_*T_*FF_];
__device__ __half g_pall[T_*PALLN_];
__device__ __half g_posh[T_*D_];
__device__ float  g_bqkv[L_*QKVN_];

// transposed fp16 weights: Wt[n][k] (round-to-nearest)
__device__ __half g_wqkvh[L_*QKVN_*D_];
__device__ __half g_woh[L_*D_*D_];
__device__ __half g_wph[L_*D_*D_];
__device__ __half g_w1h[L_*D_*FF_];
__device__ __half g_w2h[L_*FF_*D_];

// ---------------- PTX helpers (family-portable: sm_80+ ISA only) ----------
__device__ __forceinline__ uint32_t s2u(const void* p) {
    uint32_t a;
    asm("{ .reg .u64 t; cvta.to.shared.u64 t, %1; cvt.u32.u64 %0, t; }" : "=r"(a) : "l"(p));
    return a;
}

#define CPA16(sa, g) \
    asm volatile("cp.async.cg.shared.global [%0], [%1], 16;" :: "r"(sa), "l"(g) : "memory")
#define CPCOMMIT() asm volatile("cp.async.commit_group;" ::: "memory")
#define CPWAIT(n)  asm volatile("cp.async.wait_group %0;" :: "n"(n) : "memory")

#define LDSM4(d0, d1, d2, d3, a) \
    asm volatile("ldmatrix.sync.aligned.m8n8.x4.shared.b16 {%0,%1,%2,%3}, [%4];" \
        : "=r"(d0), "=r"(d1), "=r"(d2), "=r"(d3) : "r"(a))

#define MMA16816(c, a, b0, b1) \
    asm volatile("mma.sync.aligned.m16n8k16.row.col.f32.f16.f16.f32 " \
        "{%0,%1,%2,%3}, {%4,%5,%6,%7}, {%8,%9}, {%0,%1,%2,%3};" \
        : "+f"((c)[0]), "+f"((c)[1]), "+f"((c)[2]), "+f"((c)[3]) \
        : "r"((a)[0]), "r"((a)[1]), "r"((a)[2]), "r"((a)[3]), "r"(b0), "r"(b1))

// ---------------- elementwise scale: x = xs * sqrt(D) ----------------
__global__ void scale_kernel(const float* __restrict__ xs, float s) {
    int i = blockIdx.x * blockDim.x + threadIdx.x;
    g_x[i] = xs[i] * s;
}

// ---------------- pos_emb -> fp16 ----------------
__global__ void posconv_kernel(const float* __restrict__ pos) {
    int i = blockIdx.x * blockDim.x + threadIdx.x;
    g_posh[i] = __float2half_rn(pos[i]);
}

// ---------------- bias concat for fused QKV ----------------
__global__ void bcat_kernel(const float* __restrict__ bq, const float* __restrict__ bk,
                            const float* __restrict__ bv) {
    int i = blockIdx.x * blockDim.x + threadIdx.x;   // L*1536
    int l = i / QKVN_, c = i % QKVN_;
    float v = (c < D_) ? bq[l * D_ + c]
            : (c < 2 * D_) ? bk[l * D_ + c - D_]
            : bv[l * D_ + c - 2 * D_];
    g_bqkv[i] = v;
}

// ---------------- merged QKV weight transpose (fp16 rn) ----------------
__global__ void wtransqkv_kernel(const float* __restrict__ Wq,
                                 const float* __restrict__ Wk,
                                 const float* __restrict__ Wv,
                                 __half* __restrict__ Th) {
    __shared__ float sm[32][33];
    int z = blockIdx.z;
    int which = z / L_, l = z % L_;
    const size_t DD = (size_t)D_ * D_;
    const float* Wl = (which == 0 ? Wq : which == 1 ? Wk : Wv) + (size_t)l * DD;
    __half* Thl = Th + (size_t)l * QKVN_ * D_ + (size_t)which * DD;
    int n0 = blockIdx.x * 32, k0 = blockIdx.y * 32;
    int tx = threadIdx.x, ty = threadIdx.y;
    #pragma unroll
    for (int j = 0; j < 4; j++)
        sm[ty + j * 8][tx] = Wl[(size_t)(k0 + ty + j * 8) * D_ + n0 + tx];
    __syncthreads();
    #pragma unroll
    for (int j = 0; j < 4; j++) {
        int n = ty + j * 8;
        Thl[(size_t)(n0 + n) * D_ + k0 + tx] = __float2half_rn(sm[tx][n]);
    }
}

// ---------------- generic weight transpose (fp16 rn) ----------------
__global__ void wtrans_kernel(const float* __restrict__ W, __half* __restrict__ Th,
                              int K, int N, size_t srcLS, size_t dstLS) {
    __shared__ float sm[32][33];
    const float* Wl = W + (size_t)blockIdx.z * srcLS;
    __half* Thl = Th + (size_t)blockIdx.z * dstLS;
    int n0 = blockIdx.x * 32, k0 = blockIdx.y * 32;
    int tx = threadIdx.x, ty = threadIdx.y;
    #pragma unroll
    for (int j = 0; j < 4; j++)
        sm[ty + j * 8][tx] = Wl[(size_t)(k0 + ty + j * 8) * N + n0 + tx];
    __syncthreads();
    #pragma unroll
    for (int j = 0; j < 4; j++) {
        int n = ty + j * 8;
        Thl[(size_t)(n0 + n) * K + k0 + tx] = __float2half_rn(sm[tx][n]);
    }
}

// ---------------- LN -> fp16: one warp per row ----------------
__global__ void ln_h16_kernel(const float* __restrict__ in, __half* __restrict__ out,
                              const float* __restrict__ gam, const float* __restrict__ bet) {
#if __CUDA_ARCH__ >= 900
    cudaGridDependencySynchronize();
#endif
    int warp = threadIdx.x >> 5, lane = threadIdx.x & 31;
    int row = blockIdx.x * 8 + warp;
    const float4* x = (const float4*)(in + (size_t)row * D_);
    float4 v[4];
    float s = 0.0f, ss = 0.0f;
    #pragma unroll
    for (int j = 0; j < 4; j++) {
        v[j] = x[lane + j * 32];
        s  += v[j].x + v[j].y + v[j].z + v[j].w;
        ss += v[j].x * v[j].x + v[j].y * v[j].y + v[j].z * v[j].z + v[j].w * v[j].w;
    }
    #pragma unroll
    for (int off = 16; off; off >>= 1) {
        s  += __shfl_xor_sync(0xffffffffu, s,  off);
        ss += __shfl_xor_sync(0xffffffffu, ss, off);
    }
    float mean = s * (1.0f / D_);
    float var  = ss * (1.0f / D_) - mean * mean;
    float inv  = rsqrtf(var + 1e-5f);
    __half* y = out + (size_t)row * D_;
    #pragma unroll
    for (int j = 0; j < 4; j++) {
        int e = (lane + j * 32) * 4;
        float4 g = *(const float4*)(gam + e);
        float4 b = *(const float4*)(bet + e);
        __half2 h0 = __halves2half2(__float2half_rn((v[j].x - mean) * inv * g.x + b.x),
                                    __float2half_rn((v[j].y - mean) * inv * g.y + b.y));
        __half2 h1 = __halves2half2(__float2half_rn((v[j].z - mean) * inv * g.z + b.z),
                                    __float2half_rn((v[j].w - mean) * inv * g.w + b.w));
        *(__half2*)(y + e)     = h0;
        *(__half2*)(y + e + 2) = h1;
    }
}

// ---------------- final LN (fp32 out): one warp per row ----------------
__global__ void ln_f32_kernel(const float* __restrict__ in, float* __restrict__ out,
                              const float* __restrict__ gam, const float* __restrict__ bet) {
#if __CUDA_ARCH__ >= 900
    cudaGridDependencySynchronize();
#endif
    int warp = threadIdx.x >> 5, lane = threadIdx.x & 31;
    int row = blockIdx.x * 8 + warp;
    const float4* x = (const float4*)(in + (size_t)row * D_);
    float4 v[4];
    float s = 0.0f, ss = 0.0f;
    #pragma unroll
    for (int j = 0; j < 4; j++) {
        v[j] = x[lane + j * 32];
        s  += v[j].x + v[j].y + v[j].z + v[j].w;
        ss += v[j].x * v[j].x + v[j].y * v[j].y + v[j].z * v[j].z + v[j].w * v[j].w;
    }
    #pragma unroll
    for (int off = 16; off; off >>= 1) {
        s  += __shfl_xor_sync(0xffffffffu, s,  off);
        ss += __shfl_xor_sync(0xffffffffu, ss, off);
    }
    float mean = s * (1.0f / D_);
    float var  = ss * (1.0f / D_) - mean * mean;
    float inv  = rsqrtf(var + 1e-5f);
    float* y = out + (size_t)row * D_;
    #pragma unroll
    for (int j = 0; j < 4; j++) {
        int e = (lane + j * 32) * 4;
        float4 g = *(const float4*)(gam + e);
        float4 b = *(const float4*)(bet + e);
        float4 o;
        o.x = (v[j].x - mean) * inv * g.x + b.x;
        o.y = (v[j].y - mean) * inv * g.y + b.y;
        o.z = (v[j].z - mean) * inv * g.z + b.z;
        o.w = (v[j].w - mean) * inv * g.w + b.w;
        *(float4*)(y + e) = o;
    }
}

// ---------------- HMMA fp16 GEMM, fp16 A/B via cp.async, BK=64, PDL --------
#define STAGE_BYTES 32768
#define NSTG 3
__global__ void __launch_bounds__(256, 2)
gemm_f16a(const __half* __restrict__ Ah, const __half* __restrict__ Bh,
          const float* __restrict__ bias, const float* __restrict__ res,
          float* __restrict__ outF, __half* __restrict__ outH,
          int N, int K, int relu) {
    extern __shared__ char smem[];
    uint32_t sb = s2u(smem);
    int tid = threadIdx.x, lane = tid & 31, wid = tid >> 5;
    int wm = wid >> 2, wn = wid & 3;
    int rowBase = blockIdx.y * 128, colBase = blockIdx.x * 128;
    int sub = lane & 7, grp = lane >> 3;

    float acc[4][4][4];
    #pragma unroll
    for (int i = 0; i < 4; i++)
        #pragma unroll
        for (int j = 0; j < 4; j++)
            #pragma unroll
            for (int c = 0; c < 4; c++) acc[i][j][c] = 0.0f;

    const int NC = K >> 6;

    auto loadA = [&](int c, int buf) {
        uint32_t sbase = sb + buf * STAGE_BYTES;
        int k0 = c << 6;
        #pragma unroll
        for (int i = 0; i < 4; i++) {
            int id = tid + (i << 8);
            int row = id >> 3, ch = id & 7;
            int phys = ch ^ (row & 7);
            CPA16(sbase + row * 128 + phys * 16,
                  Ah + (size_t)(rowBase + row) * K + k0 + ch * 8);
        }
    };
    auto loadB = [&](int c, int buf) {
        uint32_t sbase = sb + buf * STAGE_BYTES + 16384u;
        int k0 = c << 6;
        #pragma unroll
        for (int i = 0; i < 4; i++) {
            int id = tid + (i << 8);
            int row = id >> 3, ch = id & 7;
            int phys = ch ^ (row & 7);
            CPA16(sbase + row * 128 + phys * 16,
                  Bh + (size_t)(colBase + row) * K + k0 + ch * 8);
        }
    };
    auto loadAB = [&](int c, int buf) { loadA(c, buf); loadB(c, buf); };

    auto compute = [&](int buf) {
        uint32_t base = sb + buf * STAGE_BYTES;
        #pragma unroll
        for (int ks = 0; ks < 4; ks++) {
            uint32_t ahf[4][4], bhf[4][2];
            int ci = 2 * ks + (grp >> 1);
            #pragma unroll
            for (int mi = 0; mi < 4; mi++) {
                int row = wm * 64 + mi * 16 + sub + (grp & 1) * 8;
                uint32_t ad = base + row * 128 + ((ci ^ (row & 7)) * 16);
                LDSM4(ahf[mi][0], ahf[mi][1], ahf[mi][2], ahf[mi][3], ad);
            }
            #pragma unroll
            for (int g = 0; g < 2; g++) {
                int row = wn * 32 + g * 16 + sub + (grp & 1) * 8;
                uint32_t ad = base + 16384u + row * 128 + ((ci ^ (row & 7)) * 16);
                uint32_t r0, r1, r2, r3;
                LDSM4(r0, r1, r2, r3, ad);
                bhf[2*g][0] = r0; bhf[2*g+1][0] = r1; bhf[2*g][1] = r2; bhf[2*g+1][1] = r3;
            }
            #pragma unroll
            for (int mi = 0; mi < 4; mi++)
                #pragma unroll
                for (int nj = 0; nj < 4; nj++)
                    MMA16816(acc[mi][nj], ahf[mi], bhf[nj][0], bhf[nj][1]);
        }
    };

    // Prologue: prefetch weight (B) stages before the dependency sync —
    // B never depends on the immediately-preceding kernel.
    loadB(0, 0);
    if (NC > 1) loadB(1, 1);
#if __CUDA_ARCH__ >= 900
    cudaGridDependencySynchronize();
#endif
    loadA(0, 0); CPCOMMIT();          // group0 = {B0, B1, A0}
    if (NC > 1) loadA(1, 1);
    CPCOMMIT();                        // group1 = {A1}
    #pragma unroll 1
    for (int c = 0; c < NC; c++) {
        int nxt = c + 2;
        CPWAIT(1);
        __syncthreads();
        if (nxt < NC) loadAB(nxt, nxt % NSTG);
        CPCOMMIT();
        compute(c % NSTG);
    }

#if __CUDA_ARCH__ >= 900
    cudaTriggerProgrammaticLaunchCompletion();   // let the next kernel start
#endif

    // --- epilogue ---
    #pragma unroll
    for (int mi = 0; mi < 4; mi++) {
        #pragma unroll
        for (int nj = 0; nj < 4; nj++) {
            int r = rowBase + wm * 64 + mi * 16 + (lane >> 2);
            int c = colBase + wn * 32 + nj * 8 + ((lane & 3) << 1);
            #pragma unroll
            for (int half_ = 0; half_ < 2; half_++) {
                int rr = r + half_ * 8;
                float v0 = acc[mi][nj][half_ * 2 + 0];
                float v1 = acc[mi][nj][half_ * 2 + 1];
                if (bias) { v0 += bias[c]; v1 += bias[c + 1]; }
                if (res) {
                    float2 rv = *(const float2*)(res + (size_t)rr * N + c);
                    v0 += rv.x; v1 += rv.y;
                }
                if (relu) { v0 = fmaxf(v0, 0.0f); v1 = fmaxf(v1, 0.0f); }
                if (outF)
                    *(float2*)(outF + (size_t)rr * N + c) = make_float2(v0, v1);
                else
                    *(__half2*)(outH + (size_t)rr * N + c) =
                        __halves2half2(__float2half_rn(v0), __float2half_rn(v1));
            }
        }
    }
}

// ---------------- Chunked local attention (half2 math, padded rows) --------
__global__ void attn_kernel(const __half* __restrict__ qkv, const __half* __restrict__ p,
                            const float* __restrict__ pbu, const float* __restrict__ pbv,
                            __half* __restrict__ o) {
#if __CUDA_ARCH__ >= 900
    cudaGridDependencySynchronize();
#endif
    int ci = blockIdx.x, h = blockIdx.y, b = blockIdx.z;
    int s0 = max((ci - LC_) * CS_, 0);
    int s1 = (ci + 1) * CS_;
    int W = s1 - s0;
    int t0 = ci * CS_;
    int tid = threadIdx.x;                    // 256 threads

    extern __shared__ char asmem[];
    __half* Ks = (__half*)asmem;              // WMAX_*AP_
    __half* Ps = Ks + WMAX_ * AP_;
    __half* QU = Ps + WMAX_ * AP_;            // 16*AP_
    __half* QV = QU + 16 * AP_;
    __half* Vs = QV + 16 * AP_;               // WMAX_*AP_ halves
    float*  SC = (float*)(Vs + WMAX_ * AP_);  // 16*WMAX_

    for (int idx = tid; idx < W * 64; idx += 256) {
        int s = idx >> 6, d = idx & 63;
        size_t gi = (size_t)((b * T_) + s0 + s) * QKVN_ + h * DK_ + d;
        Ks[s * AP_ + d] = qkv[gi + D_];
        Vs[s * AP_ + d] = qkv[gi + 2 * D_];
        Ps[s * AP_ + d] = p[(size_t)(s0 + s) * PALLN_ + h * DK_ + d];
    }
    for (int idx = tid; idx < 16 * 64; idx += 256) {
        int qi = idx >> 6, d = idx & 63;
        float qv_ = __half2float(qkv[(size_t)((b * T_) + t0 + qi) * QKVN_ + h * DK_ + d]);
        QU[qi * AP_ + d] = __float2half(qv_ + pbu[h * DK_ + d]);
        QV[qi * AP_ + d] = __float2half(qv_ + pbv[h * DK_ + d]);
    }
    __syncthreads();

    const float scale = 0.125f;
    int Wh = W >> 1;
    for (int it = tid; it < 8 * Wh; it += 256) {
        int qi = (it / Wh) * 2, s = (it % Wh) * 2;
        const __half2* qu0 = (const __half2*)(QU + qi * AP_);
        const __half2* qu1 = (const __half2*)(QU + (qi + 1) * AP_);
        const __half2* qv0 = (const __half2*)(QV + qi * AP_);
        const __half2* qv1 = (const __half2*)(QV + (qi + 1) * AP_);
        const __half2* k0p = (const __half2*)(Ks + s * AP_);
        const __half2* k1p = (const __half2*)(Ks + (s + 1) * AP_);
        const __half2* p0p = (const __half2*)(Ps + s * AP_);
        const __half2* p1p = (const __half2*)(Ps + (s + 1) * AP_);
        float a00 = 0, a01 = 0, a10 = 0, a11 = 0;
        #pragma unroll
        for (int blk = 0; blk < 8; blk++) {
            __half2 h00 = __float2half2_rn(0.0f), h01 = h00, h10 = h00, h11 = h00;
            #pragma unroll
            for (int j = 0; j < 4; j++) {
                int d2 = blk * 4 + j;
                __half2 u0 = qu0[d2], u1 = qu1[d2], w0 = qv0[d2], w1 = qv1[d2];
                __half2 kk0 = k0p[d2], kk1 = k1p[d2], pp0 = p0p[d2], pp1 = p1p[d2];
                h00 = __hfma2(u0, kk0, h00); h00 = __hfma2(w0, pp0, h00);
                h01 = __hfma2(u0, kk1, h01); h01 = __hfma2(w0, pp1, h01);
                h10 = __hfma2(u1, kk0, h10); h10 = __hfma2(w1, pp0, h10);
                h11 = __hfma2(u1, kk1, h11); h11 = __hfma2(w1, pp1, h11);
            }
            float2 f;
            f = __half22float2(h00); a00 += f.x + f.y;
            f = __half22float2(h01); a01 += f.x + f.y;
            f = __half22float2(h10); a10 += f.x + f.y;
            f = __half22float2(h11); a11 += f.x + f.y;
        }
        SC[qi * WMAX_ + s]           = a00 * scale;
        SC[qi * WMAX_ + s + 1]       = a01 * scale;
        SC[(qi + 1) * WMAX_ + s]     = a10 * scale;
        SC[(qi + 1) * WMAX_ + s + 1] = a11 * scale;
    }
    __syncthreads();

    int warp = tid >> 5, lane = tid & 31;
    for (int qi = warp; qi < 16; qi += 8) {
        float m = -1e30f;
        for (int s = lane; s < W; s += 32) m = fmaxf(m, SC[qi * WMAX_ + s]);
        #pragma unroll
        for (int off = 16; off; off >>= 1) m = fmaxf(m, __shfl_xor_sync(0xffffffffu, m, off));
        float sum = 0.0f;
        for (int s = lane; s < W; s += 32) {
            float e = expf(SC[qi * WMAX_ + s] - m);
            SC[qi * WMAX_ + s] = e;
            sum += e;
        }
        #pragma unroll
        for (int off = 16; off; off >>= 1) sum += __shfl_xor_sync(0xffffffffu, sum, off);
        float inv = 1.0f / sum;
        for (int s = lane; s < W; s += 32) SC[qi * WMAX_ + s] *= inv;
    }
    __syncthreads();

    {
        int it = tid;                       // 8 warps x 32 lanes
        int qi = (it >> 5) * 2, d2 = it & 31;
        float a00 = 0, a01 = 0, a10 = 0, a11 = 0;
        const __half2* V2 = (const __half2*)Vs;
        for (int s = 0; s < W; s++) {
            float2 fv = __half22float2(V2[s * (AP_ / 2) + d2]);
            float c0 = SC[qi * WMAX_ + s];
            float c1 = SC[(qi + 1) * WMAX_ + s];
            a00 += c0 * fv.x; a01 += c0 * fv.y;
            a10 += c1 * fv.x; a11 += c1 * fv.y;
        }
        int d = d2 * 2;
        size_t o0 = (size_t)((b * T_) + t0 + qi) * D_ + h * DK_ + d;
        *(__half2*)(o + o0)      = __halves2half2(__float2half_rn(a00), __float2half_rn(a01));
        *(__half2*)(o + o0 + D_) = __halves2half2(__float2half_rn(a10), __float2half_rn(a11));
    }
}

static const int ATTN_SMEM = (WMAX_*3 + 32) * AP_ * 2 + 16 * WMAX_ * 4;  // 41024
static const int GEMM_SMEM = NSTG * STAGE_BYTES;   // 98304

// ---------------- PDL launch helper ----------------
template <typename F, typename... A>
static inline void pdl(F f, dim3 g, dim3 b, size_t sh, A... args) {
    cudaLaunchConfig_t cfg = {};
    cfg.gridDim = g;
    cfg.blockDim = b;
    cfg.dynamicSmemBytes = sh;
    cfg.stream = 0;
    cudaLaunchAttribute attr[1];
    attr[0].id = cudaLaunchAttributeProgrammaticStreamSerialization;
    attr[0].val.programmaticStreamSerializationAllowed = 1;
    cfg.attrs = attr;
    cfg.numAttrs = 1;
    cudaLaunchKernelEx(&cfg, f, args...);
}

extern "C" void kernel_launch(void* const* d_in, const int* in_sizes, int n_in,
                              void* d_out, int out_size) {
    (void)in_sizes; (void)n_in; (void)out_size;
    const float* xs    = (const float*)d_in[0];
    const float* pos   = (const float*)d_in[1];
    // d_in[2] = mask: unused (window computed analytically)
    const float* Wq    = (const float*)d_in[3];
    const float* bq    = (const float*)d_in[4];
    const float* Wk    = (const float*)d_in[5];
    const float* bk    = (const float*)d_in[6];
    const float* Wv    = (const float*)d_in[7];
    const float* bv    = (const float*)d_in[8];
    const float* Wo    = (const float*)d_in[9];
    const float* bo    = (const float*)d_in[10];
    const float* Wp    = (const float*)d_in[11];
    const float* pbu   = (const float*)d_in[12];
    const float* pbv   = (const float*)d_in[13];
    const float* ln1s  = (const float*)d_in[14];
    const float* ln1b  = (const float*)d_in[15];
    const float* ln2s  = (const float*)d_in[16];
    const float* ln2b  = (const float*)d_in[17];
    const float* W1    = (const float*)d_in[18];
    const float* b1    = (const float*)d_in[19];
    const float* W2    = (const float*)d_in[20];
    const float* b2    = (const float*)d_in[21];
    const float* lnfs  = (const float*)d_in[22];
    const float* lnfb  = (const float*)d_in[23];

    cudaFuncSetAttribute(attn_kernel, cudaFuncAttributeMaxDynamicSharedMemorySize, ATTN_SMEM);
    cudaFuncSetAttribute(gemm_f16a,   cudaFuncAttributeMaxDynamicSharedMemorySize, GEMM_SMEM);

    void* a;
    #define SYM(p, s) cudaGetSymbolAddress(&a, s); auto* p = (decltype(&s[0]))a;
    SYM(px, g_x)  SYM(phh, g_hh)  SYM(pqkvh, g_qkvh)  SYM(poh, g_oh)  SYM(pffh, g_ffh)
    SYM(ppall, g_pall)  SYM(pposh, g_posh)  SYM(pbqkv, g_bqkv)
    SYM(pwqkvh, g_wqkvh)
    SYM(pwoh, g_woh)
    SYM(pwph, g_wph)
    SYM(pw1h, g_w1h)
    SYM(pw2h, g_w2h)
    #undef SYM

    const int M = B_ * T_;  // 4096
    const size_t DD = (size_t)D_ * D_;          // 262144
    const size_t QKVLS = (size_t)QKVN_ * D_;    // 786432
    dim3 wtb(32, 8);

    scale_kernel<<<(B_*T_*D_) / 256, 256>>>(xs, sqrtf((float)D_));
    posconv_kernel<<<(T_*D_) / 256, 256>>>(pos);
    bcat_kernel<<<(L_*QKVN_) / 256, 256>>>(bq, bk, bv);
    wtransqkv_kernel<<<dim3(16, 16, 3 * L_), wtb>>>(Wq, Wk, Wv, pwqkvh);
    wtrans_kernel<<<dim3(D_/32, D_/32, L_), wtb>>>(Wo, pwoh, D_, D_, DD, DD);
    wtrans_kernel<<<dim3(D_/32,  D_/32,  L_), wtb>>>(Wp, pwph, D_,  D_,  DD, DD);
    wtrans_kernel<<<dim3(FF_/32, D_/32,  L_), wtb>>>(W1, pw1h, D_,  FF_, (size_t)D_*FF_, (size_t)D_*FF_);
    wtrans_kernel<<<dim3(D_/32,  FF_/32, L_), wtb>>>(W2, pw2h, FF_, D_,  (size_t)FF_*D_, (size_t)FF_*D_);
    // p_all = pos_emb @ Wp (all layers, fp16 out)
    pdl(gemm_f16a, dim3(PALLN_/128, T_/128), dim3(256), (size_t)GEMM_SMEM,
        (const __half*)pposh, (const __half*)pwph,
        (const float*)nullptr, (const float*)nullptr,
        (float*)nullptr, (__half*)ppall, (int)PALLN_, (int)D_, 0);

    for (int l = 0; l < L_; l++) {
        size_t wdf = (size_t)l * D_ * FF_;

        // h = LN1(x) -> fp16
        pdl(ln_h16_kernel, dim3(M / 8), dim3(256), 0,
            (const float*)px, (__half*)phh, ln1s + l*D_, ln1b + l*D_);

        // qkv = h @ [Wq|Wk|Wv] + b -> fp16
        pdl(gemm_f16a, dim3(QKVN_/128, M/128), dim3(256), (size_t)GEMM_SMEM,
            (const __half*)phh, (const __half*)(pwqkvh + l * QKVLS),
            (const float*)(pbqkv + l * QKVN_), (const float*)nullptr,
            (float*)nullptr, (__half*)pqkvh, (int)QKVN_, (int)D_, 0);

        // attention -> o fp16
        pdl(attn_kernel, dim3(NCHUNK_, H_, B_), dim3(256), (size_t)ATTN_SMEM,
            (const __half*)pqkvh, (const __half*)(ppall + l * D_),
            pbu + l * H_ * DK_, pbv + l * H_ * DK_, (__half*)poh);

        // x = x + o @ Wo + bo
        pdl(gemm_f16a, dim3(D_/128, M/128), dim3(256), (size_t)GEMM_SMEM,
            (const __half*)poh, (const __half*)(pwoh + l * DD),
            (const float*)(bo + l*D_), (const float*)px,
            (float*)px, (__half*)nullptr, (int)D_, (int)D_, 0);

        // h2 = LN2(x) -> fp16
        pdl(ln_h16_kernel, dim3(M / 8), dim3(256), 0,
            (const float*)px, (__half*)phh, ln2s + l*D_, ln2b + l*D_);

        // ff = relu(h2 @ W1 + b1) -> fp16
        pdl(gemm_f16a, dim3(FF_/128, M/128), dim3(256), (size_t)GEMM_SMEM,
            (const __half*)phh, (const __half*)(pw1h + wdf),
            (const float*)(b1 + l*FF_), (const float*)nullptr,
            (float*)nullptr, (__half*)pffh, (int)FF_, (int)D_, 1);

        // x = x + ff @ W2 + b2
        pdl(gemm_f16a, dim3(D_/128, M/128), dim3(256), (size_t)GEMM_SMEM,
            (const __half*)pffh, (const __half*)(pw2h + wdf),
            (const float*)(b2 + l*D_), (const float*)px,
            (float*)px, (__half*)nullptr, (int)D_, (int)FF_, 0);
    }

    // out = LNf(x)  (fp32)
    pdl(ln_f32_kernel, dim3(M / 8), dim3(256), 0,
        (const float*)px, (float*)d_out, lnfs, lnfb);
}

// round 15
// speedup vs baseline: 1.1356x; 1.1356x over previous
#include <cuda_runtime.h>
#include <cuda_fp16.h>
#include <math.h>
#include <stdint.h>

// Problem constants
#define B_  8
#define T_  512
#define D_  512
#define H_  8
#define FF_ 2048
#define L_  6
#define CS_ 16
#define LC_ 4
#define DK_ 64
#define NCHUNK_ (T_ / CS_)          // 32
#define WMAX_ ((LC_ + 1) * CS_)     // 80
#define QKVN_ (3 * D_)              // 1536
#define PALLN_ (L_ * D_)            // 3072
#define AP_ 66                      // padded attention row pitch (halves)

// ---------------- scratch (device globals; no allocation) ----------------
__device__ float  g_x   [B_*T_*D_];
__device__ __half g_hh  [B_*T_*D_];     // LN output fp16
__device__ __half g_qkvh[B_*T_*QKVN_];
__device__ __half g_oh  [B_*T_*D_];
__device__ __half g_ffh [B_*T_*FF_];
__device__ __half g_pall[T_*PALLN_];
__device__ __half g_posh[T_*D_];
__device__ float  g_bqkv[L_*QKVN_];

// transposed fp16 weights: Wt[n][k] (round-to-nearest)
__device__ __half g_wqkvh[L_*QKVN_*D_];
__device__ __half g_woh[L_*D_*D_];
__device__ __half g_wph[L_*D_*D_];
__device__ __half g_w1h[L_*D_*FF_];
__device__ __half g_w2h[L_*FF_*D_];

// ---------------- PTX helpers (family-portable: sm_80+ ISA only) ----------
__device__ __forceinline__ uint32_t s2u(const void* p) {
    uint32_t a;
    asm("{ .reg .u64 t; cvta.to.shared.u64 t, %1; cvt.u32.u64 %0, t; }" : "=r"(a) : "l"(p));
    return a;
}

#define CPA16(sa, g) \
    asm volatile("cp.async.cg.shared.global [%0], [%1], 16;" :: "r"(sa), "l"(g) : "memory")
#define CPCOMMIT() asm volatile("cp.async.commit_group;" ::: "memory")
#define CPWAIT(n)  asm volatile("cp.async.wait_group %0;" :: "n"(n) : "memory")

#define LDSM4(d0, d1, d2, d3, a) \
    asm volatile("ldmatrix.sync.aligned.m8n8.x4.shared.b16 {%0,%1,%2,%3}, [%4];" \
        : "=r"(d0), "=r"(d1), "=r"(d2), "=r"(d3) : "r"(a))

#define MMA16816(c, a, b0, b1) \
    asm volatile("mma.sync.aligned.m16n8k16.row.col.f32.f16.f16.f32 " \
        "{%0,%1,%2,%3}, {%4,%5,%6,%7}, {%8,%9}, {%0,%1,%2,%3};" \
        : "+f"((c)[0]), "+f"((c)[1]), "+f"((c)[2]), "+f"((c)[3]) \
        : "r"((a)[0]), "r"((a)[1]), "r"((a)[2]), "r"((a)[3]), "r"(b0), "r"(b1))

// ---------------- elementwise scale: x = xs * sqrt(D) ----------------
__global__ void scale_kernel(const float* __restrict__ xs, float s) {
    int i = blockIdx.x * blockDim.x + threadIdx.x;
    g_x[i] = xs[i] * s;
}

// ---------------- pos_emb -> fp16 ----------------
__global__ void posconv_kernel(const float* __restrict__ pos) {
    int i = blockIdx.x * blockDim.x + threadIdx.x;
    g_posh[i] = __float2half_rn(pos[i]);
}

// ---------------- bias concat for fused QKV ----------------
__global__ void bcat_kernel(const float* __restrict__ bq, const float* __restrict__ bk,
                            const float* __restrict__ bv) {
    int i = blockIdx.x * blockDim.x + threadIdx.x;   // L*1536
    int l = i / QKVN_, c = i % QKVN_;
    float v = (c < D_) ? bq[l * D_ + c]
            : (c < 2 * D_) ? bk[l * D_ + c - D_]
            : bv[l * D_ + c - 2 * D_];
    g_bqkv[i] = v;
}

// ---------------- merged QKV weight transpose (fp16 rn) ----------------
__global__ void wtransqkv_kernel(const float* __restrict__ Wq,
                                 const float* __restrict__ Wk,
                                 const float* __restrict__ Wv,
                                 __half* __restrict__ Th) {
    __shared__ float sm[32][33];
    int z = blockIdx.z;
    int which = z / L_, l = z % L_;
    const size_t DD = (size_t)D_ * D_;
    const float* Wl = (which == 0 ? Wq : which == 1 ? Wk : Wv) + (size_t)l * DD;
    __half* Thl = Th + (size_t)l * QKVN_ * D_ + (size_t)which * DD;
    int n0 = blockIdx.x * 32, k0 = blockIdx.y * 32;
    int tx = threadIdx.x, ty = threadIdx.y;
    #pragma unroll
    for (int j = 0; j < 4; j++)
        sm[ty + j * 8][tx] = Wl[(size_t)(k0 + ty + j * 8) * D_ + n0 + tx];
    __syncthreads();
    #pragma unroll
    for (int j = 0; j < 4; j++) {
        int n = ty + j * 8;
        Thl[(size_t)(n0 + n) * D_ + k0 + tx] = __float2half_rn(sm[tx][n]);
    }
}

// ---------------- generic weight transpose (fp16 rn) ----------------
__global__ void wtrans_kernel(const float* __restrict__ W, __half* __restrict__ Th,
                              int K, int N, size_t srcLS, size_t dstLS) {
    __shared__ float sm[32][33];
    const float* Wl = W + (size_t)blockIdx.z * srcLS;
    __half* Thl = Th + (size_t)blockIdx.z * dstLS;
    int n0 = blockIdx.x * 32, k0 = blockIdx.y * 32;
    int tx = threadIdx.x, ty = threadIdx.y;
    #pragma unroll
    for (int j = 0; j < 4; j++)
        sm[ty + j * 8][tx] = Wl[(size_t)(k0 + ty + j * 8) * N + n0 + tx];
    __syncthreads();
    #pragma unroll
    for (int j = 0; j < 4; j++) {
        int n = ty + j * 8;
        Thl[(size_t)(n0 + n) * K + k0 + tx] = __float2half_rn(sm[tx][n]);
    }
}

// ---------------- LN -> fp16: one warp per row ----------------
__global__ void ln_h16_kernel(const float* __restrict__ in, __half* __restrict__ out,
                              const float* __restrict__ gam, const float* __restrict__ bet) {
    int warp = threadIdx.x >> 5, lane = threadIdx.x & 31;
    int row = blockIdx.x * 8 + warp;
    const float4* x = (const float4*)(in + (size_t)row * D_);
    float4 v[4];
    float s = 0.0f, ss = 0.0f;
    #pragma unroll
    for (int j = 0; j < 4; j++) {
        v[j] = x[lane + j * 32];
        s  += v[j].x + v[j].y + v[j].z + v[j].w;
        ss += v[j].x * v[j].x + v[j].y * v[j].y + v[j].z * v[j].z + v[j].w * v[j].w;
    }
    #pragma unroll
    for (int off = 16; off; off >>= 1) {
        s  += __shfl_xor_sync(0xffffffffu, s,  off);
        ss += __shfl_xor_sync(0xffffffffu, ss, off);
    }
    float mean = s * (1.0f / D_);
    float var  = ss * (1.0f / D_) - mean * mean;
    float inv  = rsqrtf(var + 1e-5f);
    __half* y = out + (size_t)row * D_;
    #pragma unroll
    for (int j = 0; j < 4; j++) {
        int e = (lane + j * 32) * 4;
        float4 g = *(const float4*)(gam + e);
        float4 b = *(const float4*)(bet + e);
        __half2 h0 = __halves2half2(__float2half_rn((v[j].x - mean) * inv * g.x + b.x),
                                    __float2half_rn((v[j].y - mean) * inv * g.y + b.y));
        __half2 h1 = __halves2half2(__float2half_rn((v[j].z - mean) * inv * g.z + b.z),
                                    __float2half_rn((v[j].w - mean) * inv * g.w + b.w));
        *(__half2*)(y + e)     = h0;
        *(__half2*)(y + e + 2) = h1;
    }
}

// ---------------- final LN (fp32 out): one warp per row ----------------
__global__ void ln_f32_kernel(const float* __restrict__ in, float* __restrict__ out,
                              const float* __restrict__ gam, const float* __restrict__ bet) {
    int warp = threadIdx.x >> 5, lane = threadIdx.x & 31;
    int row = blockIdx.x * 8 + warp;
    const float4* x = (const float4*)(in + (size_t)row * D_);
    float4 v[4];
    float s = 0.0f, ss = 0.0f;
    #pragma unroll
    for (int j = 0; j < 4; j++) {
        v[j] = x[lane + j * 32];
        s  += v[j].x + v[j].y + v[j].z + v[j].w;
        ss += v[j].x * v[j].x + v[j].y * v[j].y + v[j].z * v[j].z + v[j].w * v[j].w;
    }
    #pragma unroll
    for (int off = 16; off; off >>= 1) {
        s  += __shfl_xor_sync(0xffffffffu, s,  off);
        ss += __shfl_xor_sync(0xffffffffu, ss, off);
    }
    float mean = s * (1.0f / D_);
    float var  = ss * (1.0f / D_) - mean * mean;
    float inv  = rsqrtf(var + 1e-5f);
    float* y = out + (size_t)row * D_;
    #pragma unroll
    for (int j = 0; j < 4; j++) {
        int e = (lane + j * 32) * 4;
        float4 g = *(const float4*)(gam + e);
        float4 b = *(const float4*)(bet + e);
        float4 o;
        o.x = (v[j].x - mean) * inv * g.x + b.x;
        o.y = (v[j].y - mean) * inv * g.y + b.y;
        o.z = (v[j].z - mean) * inv * g.z + b.z;
        o.w = (v[j].w - mean) * inv * g.w + b.w;
        *(float4*)(y + e) = o;
    }
}

// ---------------- HMMA fp16 GEMM, fp16 A/B via cp.async, BK=64 ------------
// BM=128, BN in {128, 64}; 8 warps (2 m-rows x 4 n-cols), warp tile 64x(BN/4).
// Stage = A(16KB) + B(BN*128B); 3 stages, 2 CTAs/SM.
#define NSTG 3
template<int BN>
__global__ void __launch_bounds__(256, 2)
gemm_f16a(const __half* __restrict__ Ah, const __half* __restrict__ Bh,
          const float* __restrict__ bias, const float* __restrict__ res,
          float* __restrict__ outF, __half* __restrict__ outH,
          int N, int K, int relu) {
    constexpr int NJ    = BN / 32;            // n-frags per warp (4 or 2)
    constexpr int WNC   = BN / 4;             // cols per warp (32 or 16)
    constexpr int BITER = BN / 32;            // B loader iterations (4 or 2)
    constexpr int STGB  = 16384 + BN * 128;   // stage bytes (32KB or 24KB)
    extern __shared__ char smem[];
    uint32_t sb = s2u(smem);
    int tid = threadIdx.x, lane = tid & 31, wid = tid >> 5;
    int wm = wid >> 2, wn = wid & 3;
    int rowBase = blockIdx.y * 128, colBase = blockIdx.x * BN;
    int sub = lane & 7, grp = lane >> 3;

    float acc[4][NJ][4];
    #pragma unroll
    for (int i = 0; i < 4; i++)
        #pragma unroll
        for (int j = 0; j < NJ; j++)
            #pragma unroll
            for (int c = 0; c < 4; c++) acc[i][j][c] = 0.0f;

    const int NC = K >> 6;

    auto loadAB = [&](int c, int buf) {
        uint32_t sbase = sb + buf * STGB;
        int k0 = c << 6;
        #pragma unroll
        for (int i = 0; i < 4; i++) {
            int id = tid + (i << 8);
            int row = id >> 3, ch = id & 7;
            int phys = ch ^ (row & 7);
            CPA16(sbase + row * 128 + phys * 16,
                  Ah + (size_t)(rowBase + row) * K + k0 + ch * 8);
        }
        #pragma unroll
        for (int i = 0; i < BITER; i++) {
            int id = tid + (i << 8);
            int row = id >> 3, ch = id & 7;
            int phys = ch ^ (row & 7);
            CPA16(sbase + 16384u + row * 128 + phys * 16,
                  Bh + (size_t)(colBase + row) * K + k0 + ch * 8);
        }
    };

    auto compute = [&](int buf) {
        uint32_t base = sb + buf * STGB;
        #pragma unroll
        for (int ks = 0; ks < 4; ks++) {
            uint32_t ahf[4][4], bhf[NJ][2];
            int ci = 2 * ks + (grp >> 1);
            #pragma unroll
            for (int mi = 0; mi < 4; mi++) {
                int row = wm * 64 + mi * 16 + sub + (grp & 1) * 8;
                uint32_t ad = base + row * 128 + ((ci ^ (row & 7)) * 16);
                LDSM4(ahf[mi][0], ahf[mi][1], ahf[mi][2], ahf[mi][3], ad);
            }
            #pragma unroll
            for (int g = 0; g < NJ / 2; g++) {
                int row = wn * WNC + g * 16 + sub + (grp & 1) * 8;
                uint32_t ad = base + 16384u + row * 128 + ((ci ^ (row & 7)) * 16);
                uint32_t r0, r1, r2, r3;
                LDSM4(r0, r1, r2, r3, ad);
                bhf[2*g][0] = r0; bhf[2*g+1][0] = r1; bhf[2*g][1] = r2; bhf[2*g+1][1] = r3;
            }
            #pragma unroll
            for (int mi = 0; mi < 4; mi++)
                #pragma unroll
                for (int nj = 0; nj < NJ; nj++)
                    MMA16816(acc[mi][nj], ahf[mi], bhf[nj][0], bhf[nj][1]);
        }
    };

    loadAB(0, 0); CPCOMMIT();
    if (NC > 1) loadAB(1, 1);
    CPCOMMIT();
    #pragma unroll 1
    for (int c = 0; c < NC; c++) {
        int nxt = c + 2;
        CPWAIT(1);
        __syncthreads();
        if (nxt < NC) loadAB(nxt, nxt % NSTG);
        CPCOMMIT();
        compute(c % NSTG);
    }

    // --- epilogue ---
    #pragma unroll
    for (int mi = 0; mi < 4; mi++) {
        #pragma unroll
        for (int nj = 0; nj < NJ; nj++) {
            int r = rowBase + wm * 64 + mi * 16 + (lane >> 2);
            int c = colBase + wn * WNC + nj * 8 + ((lane & 3) << 1);
            #pragma unroll
            for (int half_ = 0; half_ < 2; half_++) {
                int rr = r + half_ * 8;
                float v0 = acc[mi][nj][half_ * 2 + 0];
                float v1 = acc[mi][nj][half_ * 2 + 1];
                if (bias) { v0 += bias[c]; v1 += bias[c + 1]; }
                if (res) {
                    float2 rv = *(const float2*)(res + (size_t)rr * N + c);
                    v0 += rv.x; v1 += rv.y;
                }
                if (relu) { v0 = fmaxf(v0, 0.0f); v1 = fmaxf(v1, 0.0f); }
                if (outF)
                    *(float2*)(outF + (size_t)rr * N + c) = make_float2(v0, v1);
                else
                    *(__half2*)(outH + (size_t)rr * N + c) =
                        __halves2half2(__float2half_rn(v0), __float2half_rn(v1));
            }
        }
    }
}

// ---------------- Chunked local attention (half2 math, padded rows) --------
__global__ void attn_kernel(const __half* __restrict__ qkv, const __half* __restrict__ p,
                            const float* __restrict__ pbu, const float* __restrict__ pbv,
                            __half* __restrict__ o) {
    int ci = blockIdx.x, h = blockIdx.y, b = blockIdx.z;
    int s0 = max((ci - LC_) * CS_, 0);
    int s1 = (ci + 1) * CS_;
    int W = s1 - s0;
    int t0 = ci * CS_;
    int tid = threadIdx.x;                    // 256 threads

    extern __shared__ char asmem[];
    __half* Ks = (__half*)asmem;              // WMAX_*AP_
    __half* Ps = Ks + WMAX_ * AP_;
    __half* QU = Ps + WMAX_ * AP_;            // 16*AP_
    __half* QV = QU + 16 * AP_;
    __half* Vs = QV + 16 * AP_;               // WMAX_*AP_ halves
    float*  SC = (float*)(Vs + WMAX_ * AP_);  // 16*WMAX_

    for (int idx = tid; idx < W * 64; idx += 256) {
        int s = idx >> 6, d = idx & 63;
        size_t gi = (size_t)((b * T_) + s0 + s) * QKVN_ + h * DK_ + d;
        Ks[s * AP_ + d] = qkv[gi + D_];
        Vs[s * AP_ + d] = qkv[gi + 2 * D_];
        Ps[s * AP_ + d] = p[(size_t)(s0 + s) * PALLN_ + h * DK_ + d];
    }
    for (int idx = tid; idx < 16 * 64; idx += 256) {
        int qi = idx >> 6, d = idx & 63;
        float qv_ = __half2float(qkv[(size_t)((b * T_) + t0 + qi) * QKVN_ + h * DK_ + d]);
        QU[qi * AP_ + d] = __float2half(qv_ + pbu[h * DK_ + d]);
        QV[qi * AP_ + d] = __float2half(qv_ + pbv[h * DK_ + d]);
    }
    __syncthreads();

    const float scale = 0.125f;
    int Wh = W >> 1;
    for (int it = tid; it < 8 * Wh; it += 256) {
        int qi = (it / Wh) * 2, s = (it % Wh) * 2;
        const __half2* qu0 = (const __half2*)(QU + qi * AP_);
        const __half2* qu1 = (const __half2*)(QU + (qi + 1) * AP_);
        const __half2* qv0 = (const __half2*)(QV + qi * AP_);
        const __half2* qv1 = (const __half2*)(QV + (qi + 1) * AP_);
        const __half2* k0p = (const __half2*)(Ks + s * AP_);
        const __half2* k1p = (const __half2*)(Ks + (s + 1) * AP_);
        const __half2* p0p = (const __half2*)(Ps + s * AP_);
        const __half2* p1p = (const __half2*)(Ps + (s + 1) * AP_);
        float a00 = 0, a01 = 0, a10 = 0, a11 = 0;
        #pragma unroll
        for (int blk = 0; blk < 8; blk++) {
            __half2 h00 = __float2half2_rn(0.0f), h01 = h00, h10 = h00, h11 = h00;
            #pragma unroll
            for (int j = 0; j < 4; j++) {
                int d2 = blk * 4 + j;
                __half2 u0 = qu0[d2], u1 = qu1[d2], w0 = qv0[d2], w1 = qv1[d2];
                __half2 kk0 = k0p[d2], kk1 = k1p[d2], pp0 = p0p[d2], pp1 = p1p[d2];
                h00 = __hfma2(u0, kk0, h00); h00 = __hfma2(w0, pp0, h00);
                h01 = __hfma2(u0, kk1, h01); h01 = __hfma2(w0, pp1, h01);
                h10 = __hfma2(u1, kk0, h10); h10 = __hfma2(w1, pp0, h10);
                h11 = __hfma2(u1, kk1, h11); h11 = __hfma2(w1, pp1, h11);
            }
            float2 f;
            f = __half22float2(h00); a00 += f.x + f.y;
            f = __half22float2(h01); a01 += f.x + f.y;
            f = __half22float2(h10); a10 += f.x + f.y;
            f = __half22float2(h11); a11 += f.x + f.y;
        }
        SC[qi * WMAX_ + s]           = a00 * scale;
        SC[qi * WMAX_ + s + 1]       = a01 * scale;
        SC[(qi + 1) * WMAX_ + s]     = a10 * scale;
        SC[(qi + 1) * WMAX_ + s + 1] = a11 * scale;
    }
    __syncthreads();

    int warp = tid >> 5, lane = tid & 31;
    for (int qi = warp; qi < 16; qi += 8) {
        float m = -1e30f;
        for (int s = lane; s < W; s += 32) m = fmaxf(m, SC[qi * WMAX_ + s]);
        #pragma unroll
        for (int off = 16; off; off >>= 1) m = fmaxf(m, __shfl_xor_sync(0xffffffffu, m, off));
        float sum = 0.0f;
        for (int s = lane; s < W; s += 32) {
            float e = expf(SC[qi * WMAX_ + s] - m);
            SC[qi * WMAX_ + s] = e;
            sum += e;
        }
        #pragma unroll
        for (int off = 16; off; off >>= 1) sum += __shfl_xor_sync(0xffffffffu, sum, off);
        float inv = 1.0f / sum;
        for (int s = lane; s < W; s += 32) SC[qi * WMAX_ + s] *= inv;
    }
    __syncthreads();

    {
        int it = tid;                       // 8 warps x 32 lanes
        int qi = (it >> 5) * 2, d2 = it & 31;
        float a00 = 0, a01 = 0, a10 = 0, a11 = 0;
        const __half2* V2 = (const __half2*)Vs;
        for (int s = 0; s < W; s++) {
            float2 fv = __half22float2(V2[s * (AP_ / 2) + d2]);
            float c0 = SC[qi * WMAX_ + s];
            float c1 = SC[(qi + 1) * WMAX_ + s];
            a00 += c0 * fv.x; a01 += c0 * fv.y;
            a10 += c1 * fv.x; a11 += c1 * fv.y;
        }
        int d = d2 * 2;
        size_t o0 = (size_t)((b * T_) + t0 + qi) * D_ + h * DK_ + d;
        *(__half2*)(o + o0)      = __halves2half2(__float2half_rn(a00), __float2half_rn(a01));
        *(__half2*)(o + o0 + D_) = __halves2half2(__float2half_rn(a10), __float2half_rn(a11));
    }
}

static const int ATTN_SMEM   = (WMAX_*3 + 32) * AP_ * 2 + 16 * WMAX_ * 4;  // 41024
static const int GEMM_SMEM128 = NSTG * (16384 + 128 * 128);   // 98304
static const int GEMM_SMEM64  = NSTG * (16384 + 64 * 128);    // 73728

extern "C" void kernel_launch(void* const* d_in, const int* in_sizes, int n_in,
                              void* d_out, int out_size) {
    (void)in_sizes; (void)n_in; (void)out_size;
    const float* xs    = (const float*)d_in[0];
    const float* pos   = (const float*)d_in[1];
    // d_in[2] = mask: unused (window computed analytically)
    const float* Wq    = (const float*)d_in[3];
    const float* bq    = (const float*)d_in[4];
    const float* Wk    = (const float*)d_in[5];
    const float* bk    = (const float*)d_in[6];
    const float* Wv    = (const float*)d_in[7];
    const float* bv    = (const float*)d_in[8];
    const float* Wo    = (const float*)d_in[9];
    const float* bo    = (const float*)d_in[10];
    const float* Wp    = (const float*)d_in[11];
    const float* pbu   = (const float*)d_in[12];
    const float* pbv   = (const float*)d_in[13];
    const float* ln1s  = (const float*)d_in[14];
    const float* ln1b  = (const float*)d_in[15];
    const float* ln2s  = (const float*)d_in[16];
    const float* ln2b  = (const float*)d_in[17];
    const float* W1    = (const float*)d_in[18];
    const float* b1    = (const float*)d_in[19];
    const float* W2    = (const float*)d_in[20];
    const float* b2    = (const float*)d_in[21];
    const float* lnfs  = (const float*)d_in[22];
    const float* lnfb  = (const float*)d_in[23];

    cudaFuncSetAttribute(attn_kernel,    cudaFuncAttributeMaxDynamicSharedMemorySize, ATTN_SMEM);
    cudaFuncSetAttribute(gemm_f16a<128>, cudaFuncAttributeMaxDynamicSharedMemorySize, GEMM_SMEM128);
    cudaFuncSetAttribute(gemm_f16a<64>,  cudaFuncAttributeMaxDynamicSharedMemorySize, GEMM_SMEM64);

    void* a;
    #define SYM(p, s) cudaGetSymbolAddress(&a, s); auto* p = (decltype(&s[0]))a;
    SYM(px, g_x)  SYM(phh, g_hh)  SYM(pqkvh, g_qkvh)  SYM(poh, g_oh)  SYM(pffh, g_ffh)
    SYM(ppall, g_pall)  SYM(pposh, g_posh)  SYM(pbqkv, g_bqkv)
    SYM(pwqkvh, g_wqkvh)
    SYM(pwoh, g_woh)
    SYM(pwph, g_wph)
    SYM(pw1h, g_w1h)
    SYM(pw2h, g_w2h)
    #undef SYM

    const int M = B_ * T_;  // 4096
    const size_t DD = (size_t)D_ * D_;          // 262144
    const size_t QKVLS = (size_t)QKVN_ * D_;    // 786432
    dim3 wtb(32, 8);

    scale_kernel<<<(B_*T_*D_) / 256, 256>>>(xs, sqrtf((float)D_));
    posconv_kernel<<<(T_*D_) / 256, 256>>>(pos);
    bcat_kernel<<<(L_*QKVN_) / 256, 256>>>(bq, bk, bv);
    wtransqkv_kernel<<<dim3(16, 16, 3 * L_), wtb>>>(Wq, Wk, Wv, pwqkvh);
    wtrans_kernel<<<dim3(D_/32, D_/32, L_), wtb>>>(Wo, pwoh, D_, D_, DD, DD);
    wtrans_kernel<<<dim3(D_/32,  D_/32,  L_), wtb>>>(Wp, pwph, D_,  D_,  DD, DD);
    wtrans_kernel<<<dim3(FF_/32, D_/32,  L_), wtb>>>(W1, pw1h, D_,  FF_, (size_t)D_*FF_, (size_t)D_*FF_);
    wtrans_kernel<<<dim3(D_/32,  FF_/32, L_), wtb>>>(W2, pw2h, FF_, D_,  (size_t)FF_*D_, (size_t)FF_*D_);
    // p_all = pos_emb @ Wp (all layers, fp16 out)
    gemm_f16a<128><<<dim3(PALLN_/128, T_/128), 256, GEMM_SMEM128>>>(pposh, pwph,
        nullptr, nullptr, nullptr, ppall, PALLN_, D_, 0);

    for (int l = 0; l < L_; l++) {
        size_t wdf = (size_t)l * D_ * FF_;

        // h = LN1(x) -> fp16
        ln_h16_kernel<<<M / 8, 256>>>(px, phh, ln1s + l*D_, ln1b + l*D_);

        // qkv = h @ [Wq|Wk|Wv] + b -> fp16
        gemm_f16a<128><<<dim3(QKVN_/128, M/128), 256, GEMM_SMEM128>>>(phh,
            pwqkvh + l * QKVLS, pbqkv + l * QKVN_, nullptr, nullptr, pqkvh, QKVN_, D_, 0);

        // attention -> o fp16
        attn_kernel<<<dim3(NCHUNK_, H_, B_), 256, ATTN_SMEM>>>(
            pqkvh, ppall + l * D_, pbu + l * H_ * DK_, pbv + l * H_ * DK_, poh);

        // x = x + o @ Wo + bo   (BN=64: 256 CTAs -> 2/SM co-residency)
        gemm_f16a<64><<<dim3(D_/64, M/128), 256, GEMM_SMEM64>>>(poh,
            pwoh + l * DD, bo + l*D_, px, px, nullptr, D_, D_, 0);

        // h2 = LN2(x) -> fp16
        ln_h16_kernel<<<M / 8, 256>>>(px, phh, ln2s + l*D_, ln2b + l*D_);

        // ff = relu(h2 @ W1 + b1) -> fp16
        gemm_f16a<128><<<dim3(FF_/128, M/128), 256, GEMM_SMEM128>>>(phh,
            pw1h + wdf, b1 + l*FF_, nullptr, nullptr, pffh, FF_, D_, 1);

        // x = x + ff @ W2 + b2  (BN=64: 256 CTAs -> 2/SM co-residency)
        gemm_f16a<64><<<dim3(D_/64, M/128), 256, GEMM_SMEM64>>>(pffh,
            pw2h + wdf, b2 + l*D_, px, px, nullptr, D_, FF_, 0);
    }

    // out = LNf(x)  (fp32)
    ln_f32_kernel<<<M / 8, 256>>>(px, (float*)d_out, lnfs, lnfb);
}